// round 11
// baseline (speedup 1.0000x reference)
#include <cuda_runtime.h>
#include <cstdint>

#define TT   512
#define BB   128
#define NIN  256
#define NH   1024
#define NOUT 32

// ---------------- device scratch ----------------
__device__ unsigned int g_idx[TT * BB * 64];      // per (t,b): up to 256 uint8 indices
__device__ int          g_cnt[TT * BB];
__device__ float        g_whT[NIN * NH];          // w_h transposed [i][h]
__device__ float        g_vpart[8 * (size_t)TT * BB * NOUT];   // per-htile LI partial traces (64 MB)

// ---------------- prep: compact (blocks 0..1023) + transpose (blocks 1024..2047) ----------------
__global__ __launch_bounds__(256) void prep_kernel(const float* __restrict__ spikes,
                                                   const float* __restrict__ w_h) {
    if (blockIdx.x >= 1024) {
        int k = (blockIdx.x - 1024) * 256 + threadIdx.x;
        int h = k >> 8;
        int i = k & 255;
        g_whT[i * NH + h] = w_h[k];
        return;
    }

    int gw   = (blockIdx.x * blockDim.x + threadIdx.x) >> 5;
    int lane = threadIdx.x & 31;
    const int NW = 8192;

    for (int u = gw; u < TT * BB; u += NW) {
        const float4* p = (const float4*)(spikes + (size_t)u * NIN) + lane * 2;
        float4 a = __ldcs(p);
        float4 b = __ldcs(p + 1);
        unsigned m8 = 0;
        m8 |= (a.x != 0.f) ? 1u   : 0u;
        m8 |= (a.y != 0.f) ? 2u   : 0u;
        m8 |= (a.z != 0.f) ? 4u   : 0u;
        m8 |= (a.w != 0.f) ? 8u   : 0u;
        m8 |= (b.x != 0.f) ? 16u  : 0u;
        m8 |= (b.y != 0.f) ? 32u  : 0u;
        m8 |= (b.z != 0.f) ? 64u  : 0u;
        m8 |= (b.w != 0.f) ? 128u : 0u;

        int c  = __popc(m8);
        int sc = c;
#pragma unroll
        for (int off = 1; off < 32; off <<= 1) {
            int n = __shfl_up_sync(0xffffffffu, sc, off);
            if (lane >= off) sc += n;
        }
        int tot = __shfl_sync(0xffffffffu, sc, 31);
        int ex  = sc - c;

        unsigned char* outp = (unsigned char*)g_idx + (size_t)u * 256 + ex;
        int base_i = lane << 3;
        unsigned mm = m8;
        int k = 0;
        while (mm) {
            int j = __ffs(mm) - 1; mm &= mm - 1;
            outp[k++] = (unsigned char)(base_i + j);
        }
        if (lane == 31) g_cnt[u] = tot;
    }
}

// ---------------- fused: sparse projection + LIF scan + output projection + LI scan ----------------
// Grid (8,16). Block 256 = 8 warps. Warp = (batch, 128-h tile); lane owns 4 h (LDS.128).
// R5-identical gather + LIF. Added: per-warp LI partial over this htile's spikes
// (lane = output neuron; 1 wavefront per spiking h), v_partial trace to global.
#define LIF_SMEM (NIN * 128 * 4 + 128 * NOUT * 4)

__global__ __launch_bounds__(256) void lif_kernel(const float* __restrict__ w_o) {
    extern __shared__ float s_w[];               // [NIN*128] weight tile
    float* s_wo = s_w + NIN * 128;               // [128][32] w_o slice
    int tid = threadIdx.x;
    int h0  = blockIdx.x << 7;
    int b0  = blockIdx.y << 3;

    // R5 tile load: coalesced read, permuted write (max 4-way conflicts)
    for (int k = tid; k < NIN * 128; k += 256) {
        int i = k >> 7, m = k & 127;
        float w = g_whT[i * NH + h0 + m];
        s_w[(i << 7) + ((m & 31) << 2) + (m >> 5)] = w;
    }
    // w_o slice: s_wo[hl*32+o] = w_o[o][h0+hl]
    for (int k = tid; k < 128 * NOUT; k += 256) {
        int hl = k >> 5, o = k & 31;
        s_wo[k] = w_o[o * NH + h0 + hl];
    }
    __syncthreads();   // only barrier

    int lane = tid & 31;
    int b    = b0 + (tid >> 5);
    const float4* wrow = (const float4*)s_w + lane;

    size_t tb = (size_t)b;
    uint4 p0 = ((const uint4*)(g_idx + tb * 64))[0];
    uint4 p1 = ((const uint4*)(g_idx + tb * 64))[1];
    int cnt_n = g_cnt[tb];

    float v0 = 0.f, v1 = 0.f, v2 = 0.f, v3 = 0.f;
    float i0 = 0.f, i1 = 0.f, i2 = 0.f, i3 = 0.f;
    float io = 0.f, vo = 0.f;                     // LI partial state (lane = o)
    float* vout = g_vpart + ((((size_t)blockIdx.x * TT) * BB + b) << 5) + lane;

    for (int t = 0; t < TT; t++) {
        uint4 q0 = p0, q1 = p1;
        int cnt = cnt_n;
        size_t tbn = tb + BB;
        if (t + 1 < TT) {                    // prefetch next step's list
            p0 = ((const uint4*)(g_idx + tbn * 64))[0];
            p1 = ((const uint4*)(g_idx + tbn * 64))[1];
            cnt_n = g_cnt[tbn];
        }

        unsigned w8[8] = {q0.x, q0.y, q0.z, q0.w, q1.x, q1.y, q1.z, q1.w};
        int nw = cnt >> 2;

        float c0 = 0.f, c1 = 0.f, c2 = 0.f, c3 = 0.f;  // per-h chains, index order
#pragma unroll
        for (int kw = 0; kw < 8; kw++) {
            if (kw >= nw) break;
            unsigned wd = w8[kw];
#pragma unroll
            for (int s = 0; s < 4; s++) {
                float4 f = wrow[((wd >> (8 * s)) & 255u) << 5];
                c0 += f.x; c1 += f.y; c2 += f.z; c3 += f.w;
            }
        }
        for (int kw = 8; kw < nw; kw++) {    // rare (>32 actives)
            unsigned wd = g_idx[tb * 64 + kw];
#pragma unroll
            for (int s = 0; s < 4; s++) {
                float4 f = wrow[((wd >> (8 * s)) & 255u) << 5];
                c0 += f.x; c1 += f.y; c2 += f.z; c3 += f.w;
            }
        }
        int rem = cnt & 3;
        if (rem) {
            unsigned wd;
            if (nw >= 8) {
                wd = g_idx[tb * 64 + nw];
            } else {
                wd = w8[0];
#pragma unroll
                for (int k = 1; k < 8; k++) if (nw == k) wd = w8[k];
            }
#pragma unroll
            for (int s = 0; s < 3; s++) {
                if (s < rem) {
                    float4 f = wrow[((wd >> (8 * s)) & 255u) << 5];
                    c0 += f.x; c1 += f.y; c2 += f.z; c3 += f.w;
                }
            }
        }

        // CUBA LIF (exact fp32, mirrors reference op order)
        i0 = i0 * 0.875f + c0;  v0 = v0 + 0.125f * (i0 - v0);
        i1 = i1 * 0.875f + c1;  v1 = v1 + 0.125f * (i1 - v1);
        i2 = i2 * 0.875f + c2;  v2 = v2 + 0.125f * (i2 - v2);
        i3 = i3 * 0.875f + c3;  v3 = v3 + 0.125f * (i3 - v3);
        bool z0 = (v0 - 1.0f) > 0.0f; if (z0) v0 = 0.f;
        bool z1 = (v1 - 1.0f) > 0.0f; if (z1) v1 = 0.f;
        bool z2 = (v2 - 1.0f) > 0.0f; if (z2) v2 = 0.f;
        bool z3 = (v3 - 1.0f) > 0.0f; if (z3) v3 = 0.f;

        unsigned mzw[4];
        mzw[0] = __ballot_sync(0xffffffffu, z0);   // h = h0 + 0*32 + p
        mzw[1] = __ballot_sync(0xffffffffu, z1);   // h = h0 + 1*32 + p
        mzw[2] = __ballot_sync(0xffffffffu, z2);
        mzw[3] = __ballot_sync(0xffffffffu, z3);

        // output projection over this htile's spikes (warp-uniform ffs walk);
        // lane = o, each pop is one conflict-free wavefront
        float co = 0.f;
#pragma unroll
        for (int j = 0; j < 4; j++) {
            unsigned mw = mzw[j];
            while (mw) {
                int p = __ffs(mw) - 1; mw &= mw - 1;
                co += s_wo[(((j << 5) + p) << 5) + lane];
            }
        }
        // CUBA LI partial (linear -> partials sum exactly across htiles)
        io = io * 0.875f + co;
        vo = vo + 0.125f * (io - vo);
        vout[(size_t)t << 12] = vo;    // stride BB*NOUT = 4096 floats per t

        tb = tbn;
    }
}

// ---------------- final: sum 8 htile partials -> out ----------------
__global__ __launch_bounds__(256) void sum_kernel(float* __restrict__ out) {
    size_t g = (size_t)blockIdx.x * 256 + threadIdx.x;   // over 512K float4
    const size_t N4 = (size_t)TT * BB * NOUT / 4;        // 524288
    const float4* vp = (const float4*)g_vpart;
    float4 a = vp[g];
#pragma unroll
    for (int ht = 1; ht < 8; ht++) {
        float4 p = vp[(size_t)ht * N4 + g];
        a.x += p.x; a.y += p.y; a.z += p.z; a.w += p.w;
    }
    ((float4*)out)[g] = a;
}

// ---------------- launch ----------------
extern "C" void kernel_launch(void* const* d_in, const int* in_sizes, int n_in,
                              void* d_out, int out_size) {
    const float* spikes = (const float*)d_in[0];   // [512,128,256]
    const float* w_h    = (const float*)d_in[1];   // [1024,256]
    const float* w_o    = (const float*)d_in[2];   // [32,1024]
    float* out = (float*)d_out;                    // [512,128,32]

    cudaFuncSetAttribute(lif_kernel, cudaFuncAttributeMaxDynamicSharedMemorySize, LIF_SMEM);

    prep_kernel<<<2048, 256>>>(spikes, w_h);
    lif_kernel<<<dim3(NH / 128, BB / 8), 256, LIF_SMEM>>>(w_o);
    sum_kernel<<<2048, 256>>>(out);
}